// round 1
// baseline (speedup 1.0000x reference)
#include <cuda_runtime.h>
#include <cstdint>
#include <cstddef>

// Problem constants (B=4, H=8, N=2048, D=64, curvature c=1)
#define BH   32
#define NSEQ 2048
#define DDIM 64

// ---------------------------------------------------------------------------
// tf32 helpers
// ---------------------------------------------------------------------------
__device__ __forceinline__ uint32_t f2tf32(float x) {
    uint32_t u;
    asm("cvt.rna.tf32.f32 %0, %1;" : "=r"(u) : "f"(x));
    return u;
}

__device__ __forceinline__ void mma_tf32_16x8x8(float* d, const uint32_t* a, const uint32_t* b) {
    asm volatile(
        "mma.sync.aligned.m16n8k8.row.col.f32.tf32.tf32.f32 "
        "{%0,%1,%2,%3}, {%4,%5,%6,%7}, {%8,%9}, {%0,%1,%2,%3};"
        : "+f"(d[0]), "+f"(d[1]), "+f"(d[2]), "+f"(d[3])
        : "r"(a[0]), "r"(a[1]), "r"(a[2]), "r"(a[3]), "r"(b[0]), "r"(b[1]));
}

// acosh(1+t), t = max(qn+kn-2s, 0) * (2/((1-qn)(1-kn)))
// acosh(1+t) = log(1 + t + sqrt(t^2 + 2t)); sqrt.approx(0)=0 so t=0 -> 0 exactly.
__device__ __forceinline__ float hyp_dist(float s, float qnkn, float rr) {
    float diff = fmaf(-2.f, s, qnkn);
    float t = fmaxf(diff, 0.f) * rr;
    float u2 = fmaf(t, t, t + t);
    float u;
    asm("sqrt.approx.f32 %0, %1;" : "=f"(u) : "f"(u2));
    return __logf(1.f + t + u);
}

// ---------------------------------------------------------------------------
// Kernel: CTA computes a 128x128 output tile of one batch.
//  - 256 threads = 8 warps in 2(M) x 4(N); warp tile 64x32 = 4x4 m16n8k8 tiles.
//  - smem holds Q/K tiles pre-converted to tf32 and pre-scattered into exact
//    mma fragment order (XOR-swizzled against bank conflicts), plus row/col
//    norms and reciprocal denominator factors.
// ---------------------------------------------------------------------------
extern __shared__ uint32_t smem_u[];

__global__ __launch_bounds__(256, 2)
void hyp_dist_kernel(const float* __restrict__ q,
                     const float* __restrict__ k,
                     float* __restrict__ out) {
    uint32_t* qfrag = smem_u;              // 8192 u32: [rowt(8)][ks(8)][lane(32)][reg(4)]
    uint32_t* kfrag = smem_u + 8192;       // 8192 u32: [nt(16)][ks(8)][lane(32)][reg(2)]
    float* qn_s = (float*)(smem_u + 16384);  // 128
    float* rq_s = qn_s + 128;                // 128: 2/max(1-qn,eps)
    float* kn_s = rq_s + 128;                // 128
    float* rk_s = kn_s + 128;                // 128: 1/max(1-kn,eps)

    const int tid = threadIdx.x;
    const int bn = blockIdx.x;   // N tile
    const int bm = blockIdx.y;   // M tile
    const int bz = blockIdx.z;   // batch (B*H)

    const float* qb = q + ((size_t)bz * NSEQ + (size_t)bm * 128) * DDIM;
    const float* kb = k + ((size_t)bz * NSEQ + (size_t)bn * 128) * DDIM;

    // ---- Load Q tile: convert to tf32, scatter to A-fragment layout, row norms
    #pragma unroll
    for (int i = 0; i < 8; ++i) {
        int p   = tid + 256 * i;          // float4 index, 0..2047
        int row = p >> 4;                 // 0..127
        int d0  = (p & 15) << 2;          // 0..60, multiple of 4
        float4 v = *(const float4*)(qb + row * DDIM + d0);
        float part = v.x * v.x + v.y * v.y + v.z * v.z + v.w * v.w;
        part += __shfl_xor_sync(0xffffffffu, part, 1);
        part += __shfl_xor_sync(0xffffffffu, part, 2);
        part += __shfl_xor_sync(0xffffffffu, part, 4);
        part += __shfl_xor_sync(0xffffffffu, part, 8);
        if ((tid & 15) == 0) {
            qn_s[row] = part;
            rq_s[row] = 2.f / fmaxf(1.f - part, 1e-3f);
        }
        int ks  = d0 >> 3;                         // k-step 0..7
        int reg = ((row >> 3) & 1) + (((d0 >> 2) & 1) << 1);
        int blk = (((row >> 4) << 3) + ks) << 7;   // *(128)
        int off = ((row & 7) << 4) + reg;          // lane*4 + reg, j added below
        int swz = ks << 2;                         // XOR swizzle, bits 2..4
        qfrag[blk + ((off + 0) ^ swz)]  = f2tf32(v.x);
        qfrag[blk + ((off + 4) ^ swz)]  = f2tf32(v.y);
        qfrag[blk + ((off + 8) ^ swz)]  = f2tf32(v.z);
        qfrag[blk + ((off + 12) ^ swz)] = f2tf32(v.w);
    }

    // ---- Load K tile: scatter to B-fragment layout, col norms
    #pragma unroll
    for (int i = 0; i < 8; ++i) {
        int p  = tid + 256 * i;
        int n  = p >> 4;                  // 0..127
        int d0 = (p & 15) << 2;
        float4 v = *(const float4*)(kb + n * DDIM + d0);
        float part = v.x * v.x + v.y * v.y + v.z * v.z + v.w * v.w;
        part += __shfl_xor_sync(0xffffffffu, part, 1);
        part += __shfl_xor_sync(0xffffffffu, part, 2);
        part += __shfl_xor_sync(0xffffffffu, part, 4);
        part += __shfl_xor_sync(0xffffffffu, part, 8);
        if ((tid & 15) == 0) {
            kn_s[n] = part;
            rk_s[n] = 1.f / fmaxf(1.f - part, 1e-3f);
        }
        int ks   = d0 >> 3;
        int regb = (d0 >> 2) & 1;
        int blk  = (((n >> 3) << 3) + ks) << 6;    // *(64)
        int off  = ((n & 7) << 3) + regb;          // lane*2 + reg, 2j added below
        int swz  = ks << 1;                        // XOR swizzle, bits 1..3
        kfrag[blk + ((off + 0) ^ swz)] = f2tf32(v.x);
        kfrag[blk + ((off + 2) ^ swz)] = f2tf32(v.y);
        kfrag[blk + ((off + 4) ^ swz)] = f2tf32(v.z);
        kfrag[blk + ((off + 6) ^ swz)] = f2tf32(v.w);
    }

    __syncthreads();

    // ---- Main MMA loop
    const int wid  = tid >> 5;
    const int lane = tid & 31;
    const int wm   = wid >> 2;   // 0..1
    const int wn   = wid & 3;    // 0..3

    float acc[4][4][4];
    #pragma unroll
    for (int mi = 0; mi < 4; ++mi)
        #pragma unroll
        for (int ni = 0; ni < 4; ++ni)
            #pragma unroll
            for (int r = 0; r < 4; ++r) acc[mi][ni][r] = 0.f;

    #pragma unroll
    for (int ks = 0; ks < 8; ++ks) {
        uint32_t A[4][4];
        uint32_t Bf[4][2];
        const int aswz = ks << 2;
        const int bswz = ks << 1;
        #pragma unroll
        for (int mi = 0; mi < 4; ++mi) {
            const uint32_t* p = qfrag + ((((wm << 2) + mi) << 3) + ks) * 128 + ((lane << 2) ^ aswz);
            *(uint4*)A[mi] = *(const uint4*)p;
        }
        #pragma unroll
        for (int ni = 0; ni < 4; ++ni) {
            const uint32_t* p = kfrag + ((((wn << 2) + ni) << 3) + ks) * 64 + ((lane << 1) ^ bswz);
            *(uint2*)Bf[ni] = *(const uint2*)p;
        }
        #pragma unroll
        for (int mi = 0; mi < 4; ++mi)
            #pragma unroll
            for (int ni = 0; ni < 4; ++ni)
                mma_tf32_16x8x8(acc[mi][ni], A[mi], Bf[ni]);
    }

    // ---- Fused epilogue: hyperbolic distance + store
    const int g  = lane >> 2;
    const int t4 = lane & 3;
    float* obase = out + ((size_t)bz << 22);   // N*N = 2^22

    #pragma unroll
    for (int mi = 0; mi < 4; ++mi) {
        int lr0 = wm * 64 + mi * 16 + g;
        int lr1 = lr0 + 8;
        float qn0 = qn_s[lr0], rq0 = rq_s[lr0];
        float qn1 = qn_s[lr1], rq1 = rq_s[lr1];
        float* orow0 = obase + (size_t)(bm * 128 + lr0) * NSEQ + bn * 128;
        float* orow1 = obase + (size_t)(bm * 128 + lr1) * NSEQ + bn * 128;
        #pragma unroll
        for (int ni = 0; ni < 4; ++ni) {
            int lc0 = wn * 32 + ni * 8 + t4 * 2;
            float kn0 = kn_s[lc0],     rk0 = rk_s[lc0];
            float kn1 = kn_s[lc0 + 1], rk1 = rk_s[lc0 + 1];
            float2 v0, v1;
            v0.x = hyp_dist(acc[mi][ni][0], qn0 + kn0, rq0 * rk0);
            v0.y = hyp_dist(acc[mi][ni][1], qn0 + kn1, rq0 * rk1);
            v1.x = hyp_dist(acc[mi][ni][2], qn1 + kn0, rq1 * rk0);
            v1.y = hyp_dist(acc[mi][ni][3], qn1 + kn1, rq1 * rk1);
            *(float2*)(orow0 + lc0) = v0;
            *(float2*)(orow1 + lc0) = v1;
        }
    }
}

// ---------------------------------------------------------------------------
// Launch
// ---------------------------------------------------------------------------
extern "C" void kernel_launch(void* const* d_in, const int* in_sizes, int n_in,
                              void* d_out, int out_size) {
    const float* q = (const float*)d_in[0];
    const float* k = (const float*)d_in[1];
    float* out = (float*)d_out;

    // 16384 u32 fragments + 512 floats of norms = 67584 bytes dynamic smem
    const int smem_bytes = 16384 * 4 + 512 * 4;
    cudaFuncSetAttribute(hyp_dist_kernel,
                         cudaFuncAttributeMaxDynamicSharedMemorySize, smem_bytes);

    dim3 grid(NSEQ / 128, NSEQ / 128, BH);
    hyp_dist_kernel<<<grid, 256, smem_bytes>>>(q, k, out);
}

// round 3
// speedup vs baseline: 1.4211x; 1.4211x over previous
#include <cuda_runtime.h>
#include <cstdint>
#include <cstddef>

// Problem constants (B=4, H=8, N=2048, D=64, c=1)
#define BH   32
#define NSEQ 2048
#define DDIM 64

// ---------------------------------------------------------------------------
// Precomputed norms (allocation-free: __device__ globals), interleaved pairs:
//  g_qn2[i] = (||q_i||^2, 2/max(1-||q_i||^2, 1e-3))
//  g_kn2[i] = (||k_i||^2, 1/max(1-||k_i||^2, 1e-3))
// ---------------------------------------------------------------------------
__device__ float2 g_qn2[BH * NSEQ];
__device__ float2 g_kn2[BH * NSEQ];

__global__ void norm_kernel(const float* __restrict__ q, const float* __restrict__ k) {
    int i = blockIdx.x * blockDim.x + threadIdx.x;   // 0 .. BH*NSEQ-1
    const float4* qp = (const float4*)(q + (size_t)i * DDIM);
    const float4* kp = (const float4*)(k + (size_t)i * DDIM);
    float sq = 0.f, sk = 0.f;
    #pragma unroll
    for (int j = 0; j < 16; ++j) {
        float4 a = qp[j];
        sq = fmaf(a.x, a.x, fmaf(a.y, a.y, fmaf(a.z, a.z, fmaf(a.w, a.w, sq))));
        float4 b = kp[j];
        sk = fmaf(b.x, b.x, fmaf(b.y, b.y, fmaf(b.z, b.z, fmaf(b.w, b.w, sk))));
    }
    g_qn2[i] = make_float2(sq, 2.f / fmaxf(1.f - sq, 1e-3f));
    g_kn2[i] = make_float2(sk, 1.f / fmaxf(1.f - sk, 1e-3f));
}

// ---------------------------------------------------------------------------
// tf32 helpers
// ---------------------------------------------------------------------------
__device__ __forceinline__ uint32_t f2tf32(float x) {
    uint32_t u;
    asm("cvt.rna.tf32.f32 %0, %1;" : "=r"(u) : "f"(x));
    return u;
}

__device__ __forceinline__ void mma_tf32_16x8x8(float* d, const uint32_t* a, const uint32_t* b) {
    asm volatile(
        "mma.sync.aligned.m16n8k8.row.col.f32.tf32.tf32.f32 "
        "{%0,%1,%2,%3}, {%4,%5,%6,%7}, {%8,%9}, {%0,%1,%2,%3};"
        : "+f"(d[0]), "+f"(d[1]), "+f"(d[2]), "+f"(d[3])
        : "r"(a[0]), "r"(a[1]), "r"(a[2]), "r"(a[3]), "r"(b[0]), "r"(b[1]));
}

// acosh(1+t) = log(1 + t + sqrt(t^2+2t)); sqrt.approx(0)=0 so t=0 -> 0 exactly.
__device__ __forceinline__ float hyp_dist(float s, float qnkn, float rr) {
    float diff = fmaf(-2.f, s, qnkn);
    float t = fmaxf(diff, 0.f) * rr;
    float u2 = fmaf(t, t, t + t);
    float u;
    asm("sqrt.approx.f32 %0, %1;" : "=f"(u) : "f"(u2));
    return __logf(1.f + t + u);
}

// ---------------------------------------------------------------------------
// Main kernel: 64x64 output tile per CTA, 128 threads (4 warps in 2Mx2N grid,
// warp tile 32x32 = 2x4 m16n8k8). Fragments pre-scattered in smem (XOR-swizzled).
// 6 CTAs/SM for phase interleaving.
// ---------------------------------------------------------------------------
__global__ __launch_bounds__(128, 6)
void hyp64_kernel(const float* __restrict__ q,
                  const float* __restrict__ k,
                  float* __restrict__ out) {
    __shared__ __align__(16) uint32_t qfrag[4096];   // [rowt4][ks8][lane32][reg4]
    __shared__ __align__(16) uint32_t kfrag[4096];   // [nt8][ks8][lane32][reg2]
    __shared__ __align__(16) float2 qn2s[64];
    __shared__ __align__(16) float2 cn2s[64];

    const int tid  = threadIdx.x;
    const int lane = tid & 31;
    const int wid  = tid >> 5;
    const int wm   = wid >> 1;   // 0..1
    const int wn   = wid & 1;    // 0..1
    const int bn = blockIdx.x;   // N tile (0..31)
    const int bm = blockIdx.y;   // M tile (0..31)
    const int bz = blockIdx.z;   // batch

    // ---- Load + scatter A (64x64) and B (64x64) as tf32 fragments
    {
        const float4* qb = (const float4*)(q + ((size_t)bz * NSEQ + bm * 64) * DDIM);
        const float4* kb = (const float4*)(k + ((size_t)bz * NSEQ + bn * 64) * DDIM);
        const int t16  = tid >> 4;            // 0..7 (row low bits)
        const int d0   = (tid & 15) << 2;     // 0..60 (k-col base)
        const int ks   = d0 >> 3;             // 0..7
        const int bit2 = (d0 >> 2) & 1;
        const int aswz = ks << 2;
        const int bswz = ks << 1;
        #pragma unroll
        for (int i = 0; i < 8; ++i) {
            // A: row = t16 + 8i -> row>>3 = i, row>>4 = i>>1, row&7 = t16
            float4 v = qb[tid + 128 * i];
            int reg = (i & 1) | (bit2 << 1);
            int blk = (((i >> 1) << 3) + ks) << 7;
            int off = (t16 << 4) + reg;
            qfrag[blk + ((off + 0) ^ aswz)]  = f2tf32(v.x);
            qfrag[blk + ((off + 4) ^ aswz)]  = f2tf32(v.y);
            qfrag[blk + ((off + 8) ^ aswz)]  = f2tf32(v.z);
            qfrag[blk + ((off + 12) ^ aswz)] = f2tf32(v.w);
            // B: n = t16 + 8i -> n>>3 = i, n&7 = t16
            float4 w = kb[tid + 128 * i];
            int blkb = ((i << 3) + ks) << 6;
            int offb = (t16 << 3) + bit2;
            kfrag[blkb + ((offb + 0) ^ bswz)] = f2tf32(w.x);
            kfrag[blkb + ((offb + 2) ^ bswz)] = f2tf32(w.y);
            kfrag[blkb + ((offb + 4) ^ bswz)] = f2tf32(w.z);
            kfrag[blkb + ((offb + 6) ^ bswz)] = f2tf32(w.w);
        }
    }
    // ---- Norm pairs -> smem
    if (tid < 64) qn2s[tid] = g_qn2[bz * NSEQ + bm * 64 + tid];
    else          cn2s[tid - 64] = g_kn2[bz * NSEQ + bn * 64 + (tid - 64)];

    __syncthreads();

    // ---- Main MMA loop (pure LDS + MMA)
    float acc[2][4][4];
    #pragma unroll
    for (int mi = 0; mi < 2; ++mi)
        #pragma unroll
        for (int ni = 0; ni < 4; ++ni)
            #pragma unroll
            for (int r = 0; r < 4; ++r) acc[mi][ni][r] = 0.f;

    #pragma unroll
    for (int s = 0; s < 8; ++s) {
        uint32_t A[2][4];
        uint32_t Bf[4][2];
        #pragma unroll
        for (int mi = 0; mi < 2; ++mi)
            *(uint4*)A[mi] = *(const uint4*)&qfrag[((((wm << 1) + mi) << 3) + s) * 128 +
                                                   ((lane << 2) ^ (s << 2))];
        #pragma unroll
        for (int ni = 0; ni < 4; ++ni)
            *(uint2*)Bf[ni] = *(const uint2*)&kfrag[((((wn << 2) + ni) << 3) + s) * 64 +
                                                    ((lane << 1) ^ (s << 1))];
        #pragma unroll
        for (int mi = 0; mi < 2; ++mi)
            #pragma unroll
            for (int ni = 0; ni < 4; ++ni)
                mma_tf32_16x8x8(acc[mi][ni], A[mi], Bf[ni]);
    }

    // ---- Fused epilogue
    const int g  = lane >> 2;
    const int t4 = lane & 3;

    float4 cn[4];   // (kn0, rk0, kn1, rk1) per ni
    #pragma unroll
    for (int ni = 0; ni < 4; ++ni)
        cn[ni] = *(const float4*)&cn2s[wn * 32 + ni * 8 + t4 * 2];

    float* ob = out + ((size_t)bz << 22) + (size_t)(bm * 64) * NSEQ + bn * 64;

    #pragma unroll
    for (int mi = 0; mi < 2; ++mi) {
        int r0 = wm * 32 + mi * 16 + g;
        float2 qa = qn2s[r0];
        float2 qc = qn2s[r0 + 8];
        float* o0 = ob + (size_t)r0 * NSEQ;
        float* o1 = o0 + (size_t)8 * NSEQ;
        #pragma unroll
        for (int ni = 0; ni < 4; ++ni) {
            int c = wn * 32 + ni * 8 + t4 * 2;
            float2 v0, v1;
            v0.x = hyp_dist(acc[mi][ni][0], qa.x + cn[ni].x, qa.y * cn[ni].y);
            v0.y = hyp_dist(acc[mi][ni][1], qa.x + cn[ni].z, qa.y * cn[ni].w);
            v1.x = hyp_dist(acc[mi][ni][2], qc.x + cn[ni].x, qc.y * cn[ni].y);
            v1.y = hyp_dist(acc[mi][ni][3], qc.x + cn[ni].z, qc.y * cn[ni].w);
            *(float2*)(o0 + c) = v0;
            *(float2*)(o1 + c) = v1;
        }
    }
}

// ---------------------------------------------------------------------------
// Launch
// ---------------------------------------------------------------------------
extern "C" void kernel_launch(void* const* d_in, const int* in_sizes, int n_in,
                              void* d_out, int out_size) {
    const float* q = (const float*)d_in[0];
    const float* k = (const float*)d_in[1];
    float* out = (float*)d_out;

    norm_kernel<<<(BH * NSEQ) / 256, 256>>>(q, k);

    dim3 grid(NSEQ / 64, NSEQ / 64, BH);
    hyp64_kernel<<<grid, 128>>>(q, k, out);
}

// round 5
// speedup vs baseline: 1.6587x; 1.1671x over previous
#include <cuda_runtime.h>
#include <cstdint>
#include <cstddef>

// Problem constants (B=4, H=8, N=2048, D=64, c=1)
#define BH   32
#define NSEQ 2048
#define DDIM 64
#define TILE_M 128
#define TILE_N 64

// ---------------------------------------------------------------------------
// Precomputed norms (allocation-free: __device__ globals), interleaved pairs:
//  g_qn2[i] = (||q_i||^2, 2/max(1-||q_i||^2, 1e-3))
//  g_kn2[i] = (||k_i||^2, 1/max(1-||k_i||^2, 1e-3))
// ---------------------------------------------------------------------------
__device__ float2 g_qn2[BH * NSEQ];
__device__ float2 g_kn2[BH * NSEQ];

__global__ void norm_kernel(const float* __restrict__ q, const float* __restrict__ k) {
    int i = blockIdx.x * blockDim.x + threadIdx.x;   // 0 .. BH*NSEQ-1
    const float4* qp = (const float4*)(q + (size_t)i * DDIM);
    const float4* kp = (const float4*)(k + (size_t)i * DDIM);
    float sq = 0.f, sk = 0.f;
    #pragma unroll
    for (int j = 0; j < 16; ++j) {
        float4 a = qp[j];
        sq = fmaf(a.x, a.x, fmaf(a.y, a.y, fmaf(a.z, a.z, fmaf(a.w, a.w, sq))));
        float4 b = kp[j];
        sk = fmaf(b.x, b.x, fmaf(b.y, b.y, fmaf(b.z, b.z, fmaf(b.w, b.w, sk))));
    }
    g_qn2[i] = make_float2(sq, 2.f / fmaxf(1.f - sq, 1e-3f));
    g_kn2[i] = make_float2(sk, 1.f / fmaxf(1.f - sk, 1e-3f));
}

// ---------------------------------------------------------------------------
// MMA + epilogue helpers
// ---------------------------------------------------------------------------
__device__ __forceinline__ void mma_tf32_16x8x8(float* d, const uint32_t* a, const uint32_t* b) {
    asm volatile(
        "mma.sync.aligned.m16n8k8.row.col.f32.tf32.tf32.f32 "
        "{%0,%1,%2,%3}, {%4,%5,%6,%7}, {%8,%9}, {%0,%1,%2,%3};"
        : "+f"(d[0]), "+f"(d[1]), "+f"(d[2]), "+f"(d[3])
        : "r"(a[0]), "r"(a[1]), "r"(a[2]), "r"(a[3]), "r"(b[0]), "r"(b[1]));
}

// acosh(1+t) = log(1 + t + sqrt(t^2+2t)); sqrt.approx(0)=0 so t=0 -> 0 exactly.
__device__ __forceinline__ float hyp_dist(float s, float qnkn, float rr) {
    float diff = fmaf(-2.f, s, qnkn);
    float t = fmaxf(diff, 0.f) * rr;
    float u2 = fmaf(t, t, t + t);
    float u;
    asm("sqrt.approx.f32 %0, %1;" : "=f"(u) : "f"(u2));
    return __logf(1.f + t + u);
}

// ---------------------------------------------------------------------------
// Main kernel: 128x64 output tile per CTA, 128 threads = 4 warps (2M x 2N),
// warp tile 64x32 = 4x4 m16n8k8.
//
// SoA fragment smem layout (A, 128x64):
//   subtile (mt = r>>4, s = c>>3): 16x8 = 128 words at (mt*8+s)*128
//   plane p = (r>>3 & 1) | ((c>>2 & 1) << 1), 32 words each
//   word-in-plane = ((r&7) ^ (c>>2 & 7))*4 + (c&3)
// Producer: float4 of row r, cols 4j..4j+3 -> ONE STS.128, conflict-free.
// Consumer: a0..a3 at word (lane ^ ((2s)&7)<<2) / +32 / +64^... conflict-free
// LDS.32. B (64x64) identical with 8x8 subtiles of 2 planes.
// Raw fp32 bits are used as tf32 operands (hw truncation, within tolerance).
//
// Dynamic smem (static limit is 48 KB):
//   [0:32768)        afrag  8192 u32
//   [32768:49152)    bfrag  4096 u32
//   [49152:50176)    qn2s   128 float2
//   [50176:50688)    cn2s   64 float2
// ---------------------------------------------------------------------------
#define SM_AFRAG 0
#define SM_BFRAG 32768
#define SM_QN    49152
#define SM_CN    50176
#define SM_TOT   50688

extern __shared__ char smem_dyn[];

__global__ __launch_bounds__(128, 4)
void hyp_kernel(const float* __restrict__ q,
                const float* __restrict__ k,
                float* __restrict__ out) {
    uint32_t* afrag = (uint32_t*)(smem_dyn + SM_AFRAG);
    uint32_t* bfrag = (uint32_t*)(smem_dyn + SM_BFRAG);
    float2*   qn2s  = (float2*)(smem_dyn + SM_QN);
    float2*   cn2s  = (float2*)(smem_dyn + SM_CN);

    const int tid  = threadIdx.x;
    const int lane = tid & 31;
    const int wid  = tid >> 5;
    const int wm   = wid >> 1;   // 0..1  (M half)
    const int wn   = wid & 1;    // 0..1  (N half)
    const int bn = blockIdx.x;   // N tile (0..31)
    const int bm = blockIdx.y;   // M tile (0..15)
    const int bz = blockIdx.z;   // batch

    // ---- Producer: pure LDG.128 -> STS.128 copy into SoA fragment layout
    {
        const uint4* qb = (const uint4*)(q + ((size_t)bz * NSEQ + bm * TILE_M) * DDIM);
        const uint4* kb = (const uint4*)(k + ((size_t)bz * NSEQ + bn * TILE_N) * DDIM);
        const int j  = tid & 15;       // float4-col index 0..15 (c0 = 4j)
        const int r0 = tid >> 4;       // row low bits 0..7
        const int perm = (r0 ^ (j & 7)) << 2;
        // A: addr = (mt*8 + s)*128 + p*32 + perm ; s=j>>1, p=(i&1)|((j&1)<<1), mt=i>>1
        const int baseA = (j >> 1) * 128 + ((j & 1) << 6) + perm;
        #pragma unroll
        for (int i = 0; i < 16; ++i)
            *(uint4*)&afrag[(i >> 1) * 1024 + ((i & 1) << 5) + baseA] = qb[tid + 128 * i];
        // B: addr = (nt*8 + s)*64 + regb*32 + perm ; nt=i, regb=j&1
        const int baseB = (j >> 1) * 64 + ((j & 1) << 5) + perm;
        #pragma unroll
        for (int i = 0; i < 8; ++i)
            *(uint4*)&bfrag[i * 512 + baseB] = kb[tid + 128 * i];
    }
    // ---- Norm pairs -> smem
    qn2s[tid] = g_qn2[bz * NSEQ + bm * TILE_M + tid];
    if (tid < 64) cn2s[tid] = g_kn2[bz * NSEQ + bn * TILE_N + tid];

    __syncthreads();

    // ---- Main MMA loop
    float acc[4][4][4];
    #pragma unroll
    for (int mi = 0; mi < 4; ++mi)
        #pragma unroll
        for (int ni = 0; ni < 4; ++ni)
            #pragma unroll
            for (int r = 0; r < 4; ++r) acc[mi][ni][r] = 0.f;

    const uint32_t* Aw = afrag + wm * 4096;   // wm*4 subtile rows * 8 steps * 128
    const uint32_t* Bw = bfrag + wn * 2048;   // wn*4 subtiles * 8 steps * 64

    #pragma unroll
    for (int s = 0; s < 8; ++s) {
        const int x0 = lane ^ (((2 * s) & 7) << 2);       // planes with j = 2s
        const int x1 = lane ^ (((2 * s + 1) & 7) << 2);   // planes with j = 2s+1
        uint32_t A[4][4];
        uint32_t Bf[4][2];
        #pragma unroll
        for (int mi = 0; mi < 4; ++mi) {
            const uint32_t* p = Aw + mi * 1024 + s * 128;
            A[mi][0] = p[x0];           // (g,   t4)
            A[mi][1] = p[x0 + 32];      // (g+8, t4)
            A[mi][2] = p[x1 + 64];      // (g,   t4+4)
            A[mi][3] = p[x1 + 96];      // (g+8, t4+4)
        }
        #pragma unroll
        for (int ni = 0; ni < 4; ++ni) {
            const uint32_t* p = Bw + ni * 512 + s * 64;
            Bf[ni][0] = p[x0];          // (n, t4)
            Bf[ni][1] = p[x1 + 32];     // (n, t4+4)
        }
        #pragma unroll
        for (int mi = 0; mi < 4; ++mi)
            #pragma unroll
            for (int ni = 0; ni < 4; ++ni)
                mma_tf32_16x8x8(acc[mi][ni], A[mi], Bf[ni]);
    }

    // ---- Fused epilogue
    const int g  = lane >> 2;
    const int t4 = lane & 3;

    float4 cn[4];   // (kn0, rk0, kn1, rk1) per ni
    #pragma unroll
    for (int ni = 0; ni < 4; ++ni)
        cn[ni] = *(const float4*)&cn2s[wn * 32 + ni * 8 + t4 * 2];

    float* ob = out + ((size_t)bz << 22) + (size_t)(bm * TILE_M) * NSEQ + bn * TILE_N;

    #pragma unroll
    for (int mi = 0; mi < 4; ++mi) {
        int r0 = wm * 64 + mi * 16 + g;
        float2 qa = qn2s[r0];
        float2 qc = qn2s[r0 + 8];
        float* o0 = ob + (size_t)r0 * NSEQ;
        float* o1 = o0 + (size_t)8 * NSEQ;
        #pragma unroll
        for (int ni = 0; ni < 4; ++ni) {
            int c = wn * 32 + ni * 8 + t4 * 2;
            float2 v0, v1;
            v0.x = hyp_dist(acc[mi][ni][0], qa.x + cn[ni].x, qa.y * cn[ni].y);
            v0.y = hyp_dist(acc[mi][ni][1], qa.x + cn[ni].z, qa.y * cn[ni].w);
            v1.x = hyp_dist(acc[mi][ni][2], qc.x + cn[ni].x, qc.y * cn[ni].y);
            v1.y = hyp_dist(acc[mi][ni][3], qc.x + cn[ni].z, qc.y * cn[ni].w);
            *(float2*)(o0 + c) = v0;
            *(float2*)(o1 + c) = v1;
        }
    }
}

// ---------------------------------------------------------------------------
// Launch
// ---------------------------------------------------------------------------
extern "C" void kernel_launch(void* const* d_in, const int* in_sizes, int n_in,
                              void* d_out, int out_size) {
    const float* q = (const float*)d_in[0];
    const float* k = (const float*)d_in[1];
    float* out = (float*)d_out;

    norm_kernel<<<(BH * NSEQ) / 256, 256>>>(q, k);

    static int configured = -1;
    if (configured < 0) {
        cudaFuncSetAttribute(hyp_kernel,
                             cudaFuncAttributeMaxDynamicSharedMemorySize, SM_TOT);
        configured = 1;
    }

    dim3 grid(NSEQ / TILE_N, NSEQ / TILE_M, BH);
    hyp_kernel<<<grid, 128, SM_TOT>>>(q, k, out);
}